// round 16
// baseline (speedup 1.0000x reference)
#include <cuda_runtime.h>
#include <math.h>
#include <stdint.h>

#define TOK   12544
#define BATCH 4
#define LSEQ  3136
#define NWIN  256
#define NCH   49
#define CH    64

// ---------------- scratch ----------------
__device__ float g_qkv[TOK*384];
__device__ float g_awb[TOK*128];
__device__ float g_attn[TOK*128];
__device__ float g_xz[TOK*512];
__device__ float g_xc[TOK*256];
__device__ float g_xcT[256*TOK];
__device__ float g_dtT[256*TOK];
__device__ float g_dbl[TOK*40];
__device__ float g_y[TOK*256];
__device__ float g_x1[TOK*128];
__device__ float g_h2[TOK*128];
__device__ float g_hid[TOK*512];
__device__ float g_hend[BATCH*NCH*256*16];
__device__ float g_hin[BATCH*NCH*256*16];
__device__ float g_sumdt[BATCH*NCH*256];

__device__ __forceinline__ float gelu_f(float x){ return 0.5f*x*(1.f+erff(x*0.70710678118f)); }
__device__ __forceinline__ uint32_t smem_u32(const void* p){
    uint32_t a; asm("{ .reg .u64 t; cvta.to.shared.u64 t, %1; cvt.u32.u64 %0, t; }" : "=r"(a) : "l"(p)); return a;
}
__device__ __forceinline__ void cpa16(uint32_t dst, const void* src){
    asm volatile("cp.async.cg.shared.global [%0], [%1], 16;" :: "r"(dst), "l"(src));
}
__device__ __forceinline__ void cpa16z(uint32_t dst, const void* src){
    asm volatile("cp.async.cg.shared.global [%0], [%1], 16, 0;" :: "r"(dst), "l"(src));
}
__device__ __forceinline__ void ldsm4(uint32_t* d, uint32_t addr){
    asm volatile("ldmatrix.sync.aligned.m8n8.x4.shared.b16 {%0,%1,%2,%3}, [%4];"
        : "=r"(d[0]),"=r"(d[1]),"=r"(d[2]),"=r"(d[3]) : "r"(addr));
}
__device__ __forceinline__ void mma8(float* c, const uint32_t* a, const uint32_t* b){
    asm volatile("mma.sync.aligned.m16n8k8.row.col.f32.tf32.tf32.f32 "
        "{%0,%1,%2,%3}, {%4,%5,%6,%7}, {%8,%9}, {%0,%1,%2,%3};"
        : "+f"(c[0]),"+f"(c[1]),"+f"(c[2]),"+f"(c[3])
        : "r"(a[0]),"r"(a[1]),"r"(a[2]),"r"(a[3]), "r"(b[0]),"r"(b[1]));
}

// ================= fused LN1 + merged qkv/in_proj GEMM =================
// grid (7, 196), 256 threads. A = LN(x[bm..bm+64)) resident in smem; B 3-stage cp.async.
// n<384 -> qkv (+qkv_b); else -> xz (+in_b).
__global__ __launch_bounds__(256)
void qkv_ln_gemm(const float* __restrict__ x,
                 const float* __restrict__ ln_g, const float* __restrict__ ln_b,
                 const float* __restrict__ qkv_w, const float* __restrict__ qkv_b,
                 const float* __restrict__ in_w, const float* __restrict__ in_b,
                 float* __restrict__ qkv, float* __restrict__ xz)
{
    extern __shared__ float sm[];
    const int NT = 128, NW = 4, MT = 2;
    uint32_t sbase = smem_u32(sm);
    int tid = threadIdx.x, wid = tid>>5, lane = tid&31;
    int warp_n = wid % NW, warp_m = wid / NW;
    int bm = blockIdx.y*64, bn = blockIdx.x*NT;
    int m0 = warp_m * MT * 16;

    // ---- LN1 into resident A buffer (staged/swizzled layout) ----
    {
        int r = tid >> 2;                 // row 0..63
        int c0 = (tid & 3) * 32;          // this thread's 32 cols = k-tile (tid&3)
        float4 xa[8];
        const float4* src = (const float4*)(x + (size_t)(bm+r)*128 + c0);
        float s = 0.f, q = 0.f;
        #pragma unroll
        for (int i=0;i<8;i++){
            xa[i] = src[i];
            s += xa[i].x + xa[i].y + xa[i].z + xa[i].w;
            q += xa[i].x*xa[i].x + xa[i].y*xa[i].y + xa[i].z*xa[i].z + xa[i].w*xa[i].w;
        }
        s += __shfl_xor_sync(~0u, s, 1); q += __shfl_xor_sync(~0u, q, 1);
        s += __shfl_xor_sync(~0u, s, 2); q += __shfl_xor_sync(~0u, q, 2);
        float mean = s * (1.f/128.f);
        float var  = q * (1.f/128.f) - mean*mean;
        float rstd = rsqrtf(var + 1e-5f);
        const float4* gv4 = (const float4*)(ln_g + c0);
        const float4* bv4 = (const float4*)(ln_b + c0);
        int ktile = tid & 3, sw = (r&7)<<2;
        float* ab = sm + ktile*2048 + r*32;
        #pragma unroll
        for (int i=0;i<8;i++){
            float4 gv = gv4[i], bv = bv4[i];
            float4 v;
            v.x = (xa[i].x-mean)*rstd*gv.x + bv.x;
            v.y = (xa[i].y-mean)*rstd*gv.y + bv.y;
            v.z = (xa[i].z-mean)*rstd*gv.z + bv.z;
            v.w = (xa[i].w-mean)*rstd*gv.w + bv.w;
            *(float4*)(ab + ((i*4) ^ sw)) = v;
        }
    }

    float acc[MT][4][4];
    #pragma unroll
    for (int i=0;i<MT;i++)
        #pragma unroll
        for (int j=0;j<4;j++)
            #pragma unroll
            for (int q=0;q<4;q++) acc[i][j][q]=0.f;

    auto issueB = [&](int kt){
        int st = kt % 3;
        uint32_t bbase = sbase + (uint32_t)(8192 + st*4096)*4;
        int kc = kt*32;
        #pragma unroll
        for (int i=0;i<4;i++){
            int ch = tid + i*256;
            int row = ch>>3, col = (ch&7)*4;
            uint32_t dst = bbase + (uint32_t)(row*32 + (col ^ ((row&7)<<2)))*4;
            int rw = bn + row;
            const float* src = (rw < 384) ? qkv_w + (size_t)rw*128 + kc + col
                                          : in_w + (size_t)(rw-384)*128 + kc + col;
            cpa16(dst, src);
        }
        asm volatile("cp.async.commit_group;" ::: "memory");
    };
    issueB(0); issueB(1);

    int a_r  = m0 + (lane&7) + ((lane>>3)&1)*8;
    int a_cq = (lane>>4)*4;
    int b_nb = warp_n*32 + ((lane>>4))*8 + (lane&7);
    int b_kq = ((lane>>3)&1)*4;

    for (int kt=0; kt<4; kt++){
        if (kt == 3) asm volatile("cp.async.wait_group 0;" ::: "memory");
        else         asm volatile("cp.async.wait_group 1;" ::: "memory");
        __syncthreads();
        if (kt+2 < 4) issueB(kt+2);
        uint32_t abase = sbase + (uint32_t)(kt*2048)*4;
        uint32_t bbase = sbase + (uint32_t)(8192 + (kt%3)*4096)*4;
        #pragma unroll
        for (int ks=0; ks<4; ks++){
            uint32_t af[MT][4];
            #pragma unroll
            for (int i=0;i<MT;i++){
                int r = a_r + i*16;
                int c = (ks*8 + a_cq) ^ ((r&7)<<2);
                ldsm4(af[i], abase + (uint32_t)(r*32 + c)*4);
            }
            uint32_t bf[2][4];
            #pragma unroll
            for (int j2=0;j2<2;j2++){
                int n = b_nb + j2*16;
                int c = (ks*8 + b_kq) ^ ((n&7)<<2);
                ldsm4(bf[j2], bbase + (uint32_t)(n*32 + c)*4);
            }
            #pragma unroll
            for (int i=0;i<MT;i++)
                #pragma unroll
                for (int j2=0;j2<2;j2++)
                    #pragma unroll
                    for (int jj=0;jj<2;jj++)
                        mma8(acc[i][2*j2+jj], af[i], &bf[j2][2*jj]);
        }
    }

    #pragma unroll
    for (int i=0;i<MT;i++){
        #pragma unroll
        for (int j=0;j<4;j++){
            int n = bn + warp_n*32 + j*8 + 2*(lane&3);
            #pragma unroll
            for (int half=0; half<2; half++){
                int m = bm + m0 + i*16 + (lane>>2) + half*8;
                float vx = acc[i][j][half*2+0];
                float vy = acc[i][j][half*2+1];
                if (bn < 384){
                    float2 bv = *(const float2*)(qkv_b + n);
                    vx += bv.x; vy += bv.y;
                    *(float2*)(qkv + (size_t)m*384 + n) = make_float2(vx, vy);
                } else {
                    int n2 = n - 384;
                    float2 bv = *(const float2*)(in_b + n2);
                    vx += bv.x; vy += bv.y;
                    *(float2*)(xz + (size_t)m*512 + n2) = make_float2(vx, vy);
                }
            }
        }
    }
}

// ================= cp.async + ldmatrix tf32 mma GEMM =================
// EPI: 0 none, 1 gelu, 3 residual(e0). NP pad. DT: fused dt_proj (e0=dtw,e1=dtb,e2=dtT out)
template<int NT, int EPI, int NP, int DT>
__global__ __launch_bounds__(256)
void mma_gemm(const float* __restrict__ A, const float* __restrict__ W,
              const float* __restrict__ bias, float* __restrict__ C,
              int Nout, int K,
              const float* __restrict__ e0, const float* __restrict__ e1,
              const float* __restrict__ e2)
{
    extern __shared__ float sm[];
    const int NW  = NT/32;
    const int MW  = 8/NW;
    const int MT  = 64/(16*MW);
    const int STG = 2048 + NT*32;
    const int BCH = (NT*8)/256;
    uint32_t sbase = smem_u32(sm);
    int tid = threadIdx.x, wid = tid>>5, lane = tid&31;
    int warp_n = wid % NW, warp_m = wid / NW;
    int bm = blockIdx.y*64, bn = blockIdx.x*NT;
    int m0 = warp_m * MT * 16;

    float acc[MT][4][4];
    #pragma unroll
    for (int i=0;i<MT;i++)
        #pragma unroll
        for (int j=0;j<4;j++)
            #pragma unroll
            for (int q=0;q<4;q++) acc[i][j][q]=0.f;

    auto issue = [&](int kt){
        int st = kt % 3;
        uint32_t abase = sbase + (uint32_t)st*STG*4;
        uint32_t bbase = abase + 2048*4;
        int kc = kt*32;
        #pragma unroll
        for (int i=0;i<2;i++){
            int ch = tid + i*256;
            int row = ch>>3, col = (ch&7)*4;
            uint32_t dst = abase + (uint32_t)(row*32 + (col ^ ((row&7)<<2)))*4;
            cpa16(dst, A + (size_t)(bm+row)*K + kc + col);
        }
        #pragma unroll
        for (int i=0;i<BCH;i++){
            int ch = tid + i*256;
            int row = ch>>3, col = (ch&7)*4;
            uint32_t dst = bbase + (uint32_t)(row*32 + (col ^ ((row&7)<<2)))*4;
            if (NP && (bn+row) >= Nout) cpa16z(dst, W);
            else cpa16(dst, W + (size_t)(bn+row)*K + kc + col);
        }
        asm volatile("cp.async.commit_group;" ::: "memory");
    };

    int KT = K >> 5;
    issue(0);
    issue(1);

    int a_r  = m0 + (lane&7) + ((lane>>3)&1)*8;
    int a_cq = (lane>>4)*4;
    int b_nb = warp_n*32 + ((lane>>4))*8 + (lane&7);
    int b_kq = ((lane>>3)&1)*4;

    for (int kt=0; kt<KT; kt++){
        if (kt == KT-1) asm volatile("cp.async.wait_group 0;" ::: "memory");
        else            asm volatile("cp.async.wait_group 1;" ::: "memory");
        __syncthreads();
        if (kt+2 < KT) issue(kt+2);

        uint32_t abase = sbase + (uint32_t)((kt%3)*STG)*4;
        uint32_t bbase = abase + 2048*4;
        #pragma unroll
        for (int ks=0; ks<4; ks++){
            uint32_t af[MT][4];
            #pragma unroll
            for (int i=0;i<MT;i++){
                int r = a_r + i*16;
                int c = (ks*8 + a_cq) ^ ((r&7)<<2);
                ldsm4(af[i], abase + (uint32_t)(r*32 + c)*4);
            }
            uint32_t bf[2][4];
            #pragma unroll
            for (int j2=0;j2<2;j2++){
                int n = b_nb + j2*16;
                int c = (ks*8 + b_kq) ^ ((n&7)<<2);
                ldsm4(bf[j2], bbase + (uint32_t)(n*32 + c)*4);
            }
            #pragma unroll
            for (int i=0;i<MT;i++)
                #pragma unroll
                for (int j2=0;j2<2;j2++)
                    #pragma unroll
                    for (int jj=0;jj<2;jj++)
                        mma8(acc[i][2*j2+jj], af[i], &bf[j2][2*jj]);
        }
    }

    if (DT) __syncthreads();      // pipeline smem about to be reused for dbl[:, :8]

    #pragma unroll
    for (int i=0;i<MT;i++){
        #pragma unroll
        for (int j=0;j<4;j++){
            int n = bn + warp_n*32 + j*8 + 2*(lane&3);
            if (NP && n >= Nout) continue;
            #pragma unroll
            for (int half=0; half<2; half++){
                int m = bm + m0 + i*16 + (lane>>2) + half*8;
                float vx = acc[i][j][half*2+0];
                float vy = acc[i][j][half*2+1];
                float2 bv = bias ? *(const float2*)(bias + n) : make_float2(0.f,0.f);
                vx += bv.x; vy += bv.y;
                size_t idx = (size_t)m*Nout + n;
                if (EPI == 1){
                    vx = gelu_f(vx); vy = gelu_f(vy);
                } else if (EPI == 3){
                    float2 r0 = *(const float2*)(e0 + idx);
                    vx += r0.x; vy += r0.y;
                }
                *(float2*)(C + idx) = make_float2(vx, vy);
                if (DT && warp_n == 0 && j == 0){
                    int r = m - bm;
                    sm[r*8 + n - bn]     = vx;
                    sm[r*8 + n - bn + 1] = vy;
                }
            }
        }
    }

    if (DT){
        // fused dt_proj: thread d computes softplus(dbl[t,:8]·dtw[d]+dtb[d]) for 64 tokens
        __syncthreads();
        int d = tid;
        float wr[8];
        #pragma unroll
        for (int k=0;k<8;k++) wr[k] = e0[d*8+k];
        float bb = e1[d];
        float vals[64];
        #pragma unroll 2
        for (int tt=0; tt<64; tt++){
            const float4* r4 = (const float4*)(sm + tt*8);
            float4 r0 = r4[0], r1 = r4[1];
            float accv = bb + r0.x*wr[0] + r0.y*wr[1] + r0.z*wr[2] + r0.w*wr[3]
                            + r1.x*wr[4] + r1.y*wr[5] + r1.z*wr[6] + r1.w*wr[7];
            vals[tt] = (accv > 20.f) ? accv : log1pf(__expf(accv));
        }
        float* dst = (float*)e2 + (size_t)d*TOK + bm;
        #pragma unroll
        for (int i=0;i<16;i++)
            ((float4*)dst)[i] = make_float4(vals[4*i+0], vals[4*i+1], vals[4*i+2], vals[4*i+3]);
    }
}

// ================= fused out_proj + gate + LN2 =================
__global__ __launch_bounds__(256)
void fused_out_gate(const float* __restrict__ y, const float* __restrict__ out_w,
                    const float* __restrict__ out_b,
                    const float* __restrict__ gate_w, const float* __restrict__ gate_b,
                    const float* __restrict__ x, const float* __restrict__ attn,
                    float* __restrict__ x1,
                    const float* __restrict__ ln_g, const float* __restrict__ ln_b,
                    float* __restrict__ h2)
{
    extern __shared__ float sm[];
    const int NT = 128, NW = 4, MT = 2;
    const int STG = 2048 + NT*32;
    float* msbuf = sm + 3*STG;
    uint32_t sbase = smem_u32(sm);
    uint32_t msbase = sbase + (uint32_t)(3*STG)*4;
    int tid = threadIdx.x, wid = tid>>5, lane = tid&31;
    int warp_n = wid % NW, warp_m = wid / NW;
    int bm = blockIdx.y*64;
    int m0 = warp_m * MT * 16;

    float acc[MT][4][4];
    #pragma unroll
    for (int i=0;i<MT;i++)
        #pragma unroll
        for (int j=0;j<4;j++)
            #pragma unroll
            for (int q=0;q<4;q++) acc[i][j][q]=0.f;

    int a_r  = m0 + (lane&7) + ((lane>>3)&1)*8;
    int a_cq = (lane>>4)*4;
    int b_nb = warp_n*32 + ((lane>>4))*8 + (lane&7);
    int b_kq = ((lane>>3)&1)*4;

    auto issueA = [&](int kt){
        int st = kt % 3;
        uint32_t abase = sbase + (uint32_t)st*STG*4;
        uint32_t bbase = abase + 2048*4;
        int kc = kt*32;
        #pragma unroll
        for (int i=0;i<2;i++){
            int ch = tid + i*256;
            int row = ch>>3, col = (ch&7)*4;
            uint32_t dst = abase + (uint32_t)(row*32 + (col ^ ((row&7)<<2)))*4;
            cpa16(dst, y + (size_t)(bm+row)*256 + kc + col);
        }
        #pragma unroll
        for (int i=0;i<4;i++){
            int ch = tid + i*256;
            int row = ch>>3, col = (ch&7)*4;
            uint32_t dst = bbase + (uint32_t)(row*32 + (col ^ ((row&7)<<2)))*4;
            cpa16(dst, out_w + (size_t)row*256 + kc + col);
        }
        asm volatile("cp.async.commit_group;" ::: "memory");
    };
    issueA(0); issueA(1);
    for (int kt=0; kt<8; kt++){
        if (kt == 7) asm volatile("cp.async.wait_group 0;" ::: "memory");
        else         asm volatile("cp.async.wait_group 1;" ::: "memory");
        __syncthreads();
        if (kt+2 < 8) issueA(kt+2);
        uint32_t abase = sbase + (uint32_t)((kt%3)*STG)*4;
        uint32_t bbase = abase + 2048*4;
        #pragma unroll
        for (int ks=0; ks<4; ks++){
            uint32_t af[MT][4];
            #pragma unroll
            for (int i=0;i<MT;i++){
                int r = a_r + i*16;
                int c = (ks*8 + a_cq) ^ ((r&7)<<2);
                ldsm4(af[i], abase + (uint32_t)(r*32 + c)*4);
            }
            uint32_t bf[2][4];
            #pragma unroll
            for (int j2=0;j2<2;j2++){
                int n = b_nb + j2*16;
                int c = (ks*8 + b_kq) ^ ((n&7)<<2);
                ldsm4(bf[j2], bbase + (uint32_t)(n*32 + c)*4);
            }
            #pragma unroll
            for (int i=0;i<MT;i++)
                #pragma unroll
                for (int j2=0;j2<2;j2++)
                    #pragma unroll
                    for (int jj=0;jj<2;jj++)
                        mma8(acc[i][2*j2+jj], af[i], &bf[j2][2*jj]);
        }
    }
    __syncthreads();
    #pragma unroll
    for (int i=0;i<MT;i++){
        #pragma unroll
        for (int j=0;j<4;j++){
            int n = warp_n*32 + j*8 + 2*(lane&3);
            float2 bv = *(const float2*)(out_b + n);
            #pragma unroll
            for (int half=0; half<2; half++){
                int r = m0 + i*16 + (lane>>2) + half*8;
                float vx = acc[i][j][half*2+0] + bv.x;
                float vy = acc[i][j][half*2+1] + bv.y;
                int ktm = n>>5, c = n&31, sw = (r&7)<<2;
                msbuf[ktm*2048 + r*32 + (c^sw)]     = vx;
                msbuf[ktm*2048 + r*32 + ((c^sw)+1)] = vy;
            }
        }
    }
    __syncthreads();

    #pragma unroll
    for (int i=0;i<MT;i++)
        #pragma unroll
        for (int j=0;j<4;j++)
            #pragma unroll
            for (int q=0;q<4;q++) acc[i][j][q]=0.f;

    auto issueB = [&](int kt){
        int st = kt % 3;
        uint32_t abase = sbase + (uint32_t)st*STG*4;
        uint32_t bbase = abase + 2048*4;
        int bcol = (kt < 4) ? 128 + kt*32 : (kt-4)*32;
        if (kt >= 4){
            int acol = (kt-4)*32;
            #pragma unroll
            for (int i=0;i<2;i++){
                int ch = tid + i*256;
                int row = ch>>3, col = (ch&7)*4;
                uint32_t dst = abase + (uint32_t)(row*32 + (col ^ ((row&7)<<2)))*4;
                cpa16(dst, attn + (size_t)(bm+row)*128 + acol + col);
            }
        }
        #pragma unroll
        for (int i=0;i<4;i++){
            int ch = tid + i*256;
            int row = ch>>3, col = (ch&7)*4;
            uint32_t dst = bbase + (uint32_t)(row*32 + (col ^ ((row&7)<<2)))*4;
            cpa16(dst, gate_w + (size_t)row*256 + bcol + col);
        }
        asm volatile("cp.async.commit_group;" ::: "memory");
    };
    issueB(0); issueB(1);
    for (int kt=0; kt<8; kt++){
        if (kt == 7) asm volatile("cp.async.wait_group 0;" ::: "memory");
        else         asm volatile("cp.async.wait_group 1;" ::: "memory");
        __syncthreads();
        if (kt+2 < 8) issueB(kt+2);
        uint32_t abase = (kt < 4) ? (msbase + (uint32_t)kt*2048*4)
                                  : (sbase + (uint32_t)((kt%3)*STG)*4);
        uint32_t bbase = sbase + (uint32_t)((kt%3)*STG)*4 + 2048*4;
        #pragma unroll
        for (int ks=0; ks<4; ks++){
            uint32_t af[MT][4];
            #pragma unroll
            for (int i=0;i<MT;i++){
                int r = a_r + i*16;
                int c = (ks*8 + a_cq) ^ ((r&7)<<2);
                ldsm4(af[i], abase + (uint32_t)(r*32 + c)*4);
            }
            uint32_t bf[2][4];
            #pragma unroll
            for (int j2=0;j2<2;j2++){
                int n = b_nb + j2*16;
                int c = (ks*8 + b_kq) ^ ((n&7)<<2);
                ldsm4(bf[j2], bbase + (uint32_t)(n*32 + c)*4);
            }
            #pragma unroll
            for (int i=0;i<MT;i++)
                #pragma unroll
                for (int j2=0;j2<2;j2++)
                    #pragma unroll
                    for (int jj=0;jj<2;jj++)
                        mma8(acc[i][2*j2+jj], af[i], &bf[j2][2*jj]);
        }
    }

    float* xs = sm;
    __syncthreads();
    #pragma unroll
    for (int i=0;i<MT;i++){
        #pragma unroll
        for (int j=0;j<4;j++){
            int n = warp_n*32 + j*8 + 2*(lane&3);
            float2 bv = *(const float2*)(gate_b + n);
            #pragma unroll
            for (int half=0; half<2; half++){
                int r = m0 + i*16 + (lane>>2) + half*8;
                int m = bm + r;
                float vx = acc[i][j][half*2+0] + bv.x;
                float vy = acc[i][j][half*2+1] + bv.y;
                size_t idx = (size_t)m*128 + n;
                float2 r0 = *(const float2*)(x + idx);
                float2 r1 = *(const float2*)(attn + idx);
                int ktm = n>>5, c = n&31, sw = (r&7)<<2;
                float m2x = msbuf[ktm*2048 + r*32 + (c^sw)];
                float m2y = msbuf[ktm*2048 + r*32 + ((c^sw)+1)];
                float gx = 1.f/(1.f+__expf(-vx));
                float gy = 1.f/(1.f+__expf(-vy));
                vx = r0.x + gx*r1.x + (1.f-gx)*m2x;
                vy = r0.y + gy*r1.y + (1.f-gy)*m2y;
                *(float2*)(x1 + idx) = make_float2(vx, vy);
                xs[r*129 + n]     = vx;
                xs[r*129 + n + 1] = vy;
            }
        }
    }
    __syncthreads();
    #pragma unroll 1
    for (int rr=0; rr<8; rr++){
        int r = wid*8 + rr;
        float v0 = xs[r*129 + lane];
        float v1 = xs[r*129 + lane + 32];
        float v2 = xs[r*129 + lane + 64];
        float v3 = xs[r*129 + lane + 96];
        float s = v0+v1+v2+v3;
        #pragma unroll
        for (int o=16;o;o>>=1) s += __shfl_xor_sync(~0u, s, o);
        float mean = s * (1.f/128.f);
        float d0=v0-mean, d1=v1-mean, d2=v2-mean, d3=v3-mean;
        float q = d0*d0+d1*d1+d2*d2+d3*d3;
        #pragma unroll
        for (int o=16;o;o>>=1) q += __shfl_xor_sync(~0u, q, o);
        float rstd = rsqrtf(q*(1.f/128.f) + 1e-5f);
        size_t mb = (size_t)(bm + r)*128;
        h2[mb + lane]      = d0*rstd*ln_g[lane]      + ln_b[lane];
        h2[mb + lane + 32] = d1*rstd*ln_g[lane + 32] + ln_b[lane + 32];
        h2[mb + lane + 64] = d2*rstd*ln_g[lane + 64] + ln_b[lane + 64];
        h2[mb + lane + 96] = d3*rstd*ln_g[lane + 96] + ln_b[lane + 96];
    }
}

// ---------------- window attention ----------------
__global__ void attn_kernel(const float* __restrict__ rpb) {
    int w = blockIdx.x >> 2;
    int head = blockIdx.x & 3;
    int b = w >> 6, wh = (w >> 3) & 7, ww = w & 7;
    __shared__ float qs[49][32], ks[49][32], vs[49][32];
    __shared__ float sc[49][49];
    int tid = threadIdx.x;
    const float scale = 0.17677669529663689f;
    for (int i = tid; i < 49*32; i += 128) {
        int n = i >> 5, d = i & 31;
        int t = ((b*56 + wh*7 + n/7)*56 + ww*7 + n%7);
        const float* base = g_qkv + (size_t)t*384 + head*32 + d;
        qs[n][d] = base[0] * scale;
        ks[n][d] = base[128];
        vs[n][d] = base[256];
    }
    __syncthreads();
    for (int idx = tid; idx < 49*49; idx += 128) {
        int i = idx/49, j = idx%49;
        float s = 0.f;
        const float4* qp = (const float4*)qs[i];
        const float4* kp = (const float4*)ks[j];
        #pragma unroll
        for (int k=0;k<8;k++){ float4 a=qp[k], c=kp[k]; s += a.x*c.x+a.y*c.y+a.z*c.z+a.w*c.w; }
        int dr = i/7 - j/7 + 6, dc = i%7 - j%7 + 6;
        sc[i][j] = s + rpb[(dr*13+dc)*4 + head];
    }
    __syncthreads();
    if (tid < 49) {
        int i = tid;
        float m = -1e30f;
        for (int j=0;j<49;j++) m = fmaxf(m, sc[i][j]);
        float sum = 0.f;
        for (int j=0;j<49;j++){ float e=__expf(sc[i][j]-m); sc[i][j]=e; sum+=e; }
        float inv = 1.f/sum;
        for (int j=0;j<49;j++) sc[i][j] *= inv;
    }
    __syncthreads();
    for (int idx = tid; idx < 49*32; idx += 128) {
        int i = idx >> 5, d = idx & 31;
        float o = 0.f;
        for (int j=0;j<49;j++) o += sc[i][j]*vs[j][d];
        int t = ((b*56 + wh*7 + i/7)*56 + ww*7 + i%7);
        g_awb[(size_t)t*128 + head*32 + d] = o;
    }
}

// ---------------- tiled causal conv (k=4) + SiLU, dual-layout output ----------------
__global__ __launch_bounds__(256) void conv_kernel(const float* __restrict__ cw,
                                                   const float* __restrict__ cb) {
    __shared__ float tile[35][256];
    int blk = blockIdx.x;
    int b = blk / 98;
    int t0 = (blk % 98) * 32;
    int tid = threadIdx.x;
    for (int idx = tid; idx < 35*256; idx += 256){
        int row = idx >> 8, col = idx & 255;
        int tg = t0 + row - 3;
        tile[row][col] = (tg >= 0) ? g_xz[((size_t)(b*LSEQ + tg))*512 + col] : 0.f;
    }
    __syncthreads();
    int d = tid;
    float w0 = cw[d*4+0], w1 = cw[d*4+1], w2 = cw[d*4+2], w3 = cw[d*4+3];
    float bb = cb[d];
    float vals[32];
    #pragma unroll 4
    for (int tt = 0; tt < 32; tt++){
        float acc = bb
            + w0*tile[tt+0][d] + w1*tile[tt+1][d]
            + w2*tile[tt+2][d] + w3*tile[tt+3][d];
        float sg = 1.f/(1.f+__expf(-acc));
        float v = acc * sg;
        vals[tt] = v;
        g_xc[((size_t)(b*LSEQ + t0 + tt))*256 + d] = v;
    }
    float* dstT = g_xcT + (size_t)d*TOK + b*LSEQ + t0;
    #pragma unroll
    for (int i=0;i<8;i++)
        ((float4*)dstT)[i] = make_float4(vals[4*i+0], vals[4*i+1], vals[4*i+2], vals[4*i+3]);
}

// ============ chunk-parallel selective scan (staged loads, block-shared B/C) ============
__global__ __launch_bounds__(256) void scan_phase1(const float* __restrict__ A_log){
    __shared__ float sdt[8][2][64], sxc[8][2][64];
    __shared__ float sB[64][16];
    int warp = threadIdx.x >> 5, lane = threadIdx.x & 31;
    int gw = blockIdx.x * 8 + warp;
    int dpair = gw & 127;
    int d = dpair*2 + (lane >> 4);
    int s = lane & 15;
    float Aval = -__expf(A_log[d*16 + s]);
    int gw0 = blockIdx.x * 8;
    int chunk = (gw0 >> 7) % NCH;
    int b = gw0 / (128*NCH);
    int tb = b*LSEQ + chunk*CH;
    {
        int tt = threadIdx.x >> 2, q = (threadIdx.x & 3)*4;
        *(float4*)&sB[tt][q] = *(const float4*)&g_dbl[(size_t)(tb+tt)*40 + 8 + q];
    }
    {
        int rr = lane >> 4, c4 = (lane & 15)*4;
        int dbase = dpair*2;
        *(float4*)&sdt[warp][rr][c4] = *(const float4*)&g_dtT[(size_t)(dbase+rr)*TOK + tb + c4];
        *(float4*)&sxc[warp][rr][c4] = *(const float4*)&g_xcT[(size_t)(dbase+rr)*TOK + tb + c4];
    }
    __syncthreads();
    int rr = lane >> 4;
    float h = 0.f, sd = 0.f;
    #pragma unroll 1
    for (int g = 0; g < CH; g += 8) {
        #pragma unroll
        for (int u=0;u<8;u++){
            float dtv = sdt[warp][rr][g+u];
            float xcv = sxc[warp][rr][g+u];
            float Bv  = sB[g+u][s];
            sd += dtv;
            float a = __expf(dtv*Aval);
            h = a*h + dtv*Bv*xcv;
        }
    }
    size_t hidx = ((size_t)(b*NCH + chunk)*256 + d)*16 + s;
    g_hend[hidx] = h;
    if (s == 0) g_sumdt[(b*NCH + chunk)*256 + d] = sd;
}

__global__ __launch_bounds__(128) void scan_phase2(const float* __restrict__ A_log){
    int gw = (blockIdx.x*blockDim.x + threadIdx.x) >> 5;
    int lane = threadIdx.x & 31;
    int b = gw >> 7;
    int dpair = gw & 127;
    int d = dpair*2 + (lane >> 4);
    int s = lane & 15;
    float Aval = -__expf(A_log[d*16 + s]);
    float h = 0.f;
    size_t hb = ((size_t)(b*NCH)*256 + d)*16 + s;
    int    sb = (b*NCH)*256 + d;
    #pragma unroll 1
    for (int c0 = 0; c0 < 48; c0 += 8){
        float sd[8], he[8];
        #pragma unroll
        for (int u=0;u<8;u++){
            sd[u] = g_sumdt[sb + (c0+u)*256];
            he[u] = g_hend[hb + (size_t)(c0+u)*4096];
        }
        float dec[8];
        #pragma unroll
        for (int u=0;u<8;u++) dec[u] = __expf(Aval*sd[u]);
        #pragma unroll
        for (int u=0;u<8;u++){
            g_hin[hb + (size_t)(c0+u)*4096] = h;
            h = dec[u]*h + he[u];
        }
    }
    g_hin[hb + (size_t)48*4096] = h;
}

__global__ __launch_bounds__(256) void scan_phase3(const float* __restrict__ A_log,
                                                   const float* __restrict__ Dp){
    __shared__ float part[8*32*33];
    __shared__ float sdt[8][2][64], sxc[8][2][64];
    __shared__ float sB[64][16], sC[64][16];
    int warp = threadIdx.x >> 5, lane = threadIdx.x & 31;
    int gw = blockIdx.x * 8 + warp;
    int dpair = gw & 127;
    int dbase = dpair*2;
    int d = dbase + (lane >> 4);
    int s = lane & 15;
    float Aval = -__expf(A_log[d*16 + s]);
    float dp0 = Dp[dbase], dp1 = Dp[dbase+1];
    int gw0 = blockIdx.x * 8;
    int chunk = (gw0 >> 7) % NCH;
    int b = gw0 / (128*NCH);
    int tb = b*LSEQ + chunk*CH;
    size_t hidx = ((size_t)(b*NCH + chunk)*256 + d)*16 + s;
    float h = g_hin[hidx];
    float* pp = part + warp*32*33 + lane*33;
    float* wp = part + warp*32*33;
    {
        int tt = threadIdx.x >> 2, q = (threadIdx.x & 3)*4;
        *(float4*)&sB[tt][q] = *(const float4*)&g_dbl[(size_t)(tb+tt)*40 + 8 + q];
        *(float4*)&sC[tt][q] = *(const float4*)&g_dbl[(size_t)(tb+tt)*40 + 24 + q];
    }
    {
        int rr = lane >> 4, c4 = (lane & 15)*4;
        *(float4*)&sdt[warp][rr][c4] = *(const float4*)&g_dtT[(size_t)(dbase+rr)*TOK + tb + c4];
        *(float4*)&sxc[warp][rr][c4] = *(const float4*)&g_xcT[(size_t)(dbase+rr)*TOK + tb + c4];
    }
    __syncthreads();
    int rr = lane >> 4;
    #pragma unroll 1
    for (int half = 0; half < 2; half++) {
        int base = half*32;
        #pragma unroll 1
        for (int g = 0; g < 32; g += 8) {
            #pragma unroll
            for (int u=0;u<8;u++){
                float dtv = sdt[warp][rr][base+g+u];
                float xcv = sxc[warp][rr][base+g+u];
                float Bv  = sB[base+g+u][s];
                float Cv  = sC[base+g+u][s];
                float a = __expf(dtv*Aval);
                h = a*h + dtv*Bv*xcv;
                pp[g+u] = h * Cv;
            }
        }
        __syncwarp();
        {
            int lu = lane;
            int t = tb + base + lu;
            float y0 = 0.f, y1 = 0.f;
            #pragma unroll
            for (int ss=0; ss<16; ss++){
                y0 += wp[ss*33 + lu];
                y1 += wp[(16+ss)*33 + lu];
            }
            float xc0 = sxc[warp][0][base+lu];
            float xc1 = sxc[warp][1][base+lu];
            float2 zv = *(const float2*)&g_xz[(size_t)t*512 + 256 + dbase];
            float yv0 = y0 + xc0*dp0;
            float yv1 = y1 + xc1*dp1;
            float sg0 = 1.f/(1.f+__expf(-zv.x));
            float sg1 = 1.f/(1.f+__expf(-zv.y));
            *(float2*)&g_y[(size_t)t*256 + dbase] = make_float2(yv0*zv.x*sg0, yv1*zv.y*sg1);
        }
        __syncwarp();
    }
}

// ---------------- launch ----------------
extern "C" void kernel_launch(void* const* d_in, const int* in_sizes, int n_in,
                              void* d_out, int out_size) {
    const float* x        = (const float*)d_in[0];
    const float* ln1_g    = (const float*)d_in[1];
    const float* ln1_b    = (const float*)d_in[2];
    const float* qkv_w    = (const float*)d_in[3];
    const float* qkv_b    = (const float*)d_in[4];
    const float* rpb      = (const float*)d_in[5];
    const float* proj_w   = (const float*)d_in[6];
    const float* proj_b   = (const float*)d_in[7];
    const float* in_w     = (const float*)d_in[8];
    const float* in_b     = (const float*)d_in[9];
    const float* conv_w   = (const float*)d_in[10];
    const float* conv_b   = (const float*)d_in[11];
    const float* xproj_w  = (const float*)d_in[12];
    const float* dtw      = (const float*)d_in[13];
    const float* dtb      = (const float*)d_in[14];
    const float* A_log    = (const float*)d_in[15];
    const float* Dp       = (const float*)d_in[16];
    const float* out_w    = (const float*)d_in[17];
    const float* out_b    = (const float*)d_in[18];
    const float* gate_w   = (const float*)d_in[19];
    const float* gate_b   = (const float*)d_in[20];
    const float* ln2_g    = (const float*)d_in[21];
    const float* ln2_b    = (const float*)d_in[22];
    const float* mlp_w1   = (const float*)d_in[23];
    const float* mlp_b1   = (const float*)d_in[24];
    const float* mlp_w2   = (const float*)d_in[25];
    const float* mlp_b2   = (const float*)d_in[26];
    float* out = (float*)d_out;

    float *qkv, *awb, *attn, *xz, *y, *x1, *h2, *hid, *xc, *dbl, *dtT;
    cudaGetSymbolAddress((void**)&qkv,   g_qkv);
    cudaGetSymbolAddress((void**)&awb,   g_awb);
    cudaGetSymbolAddress((void**)&attn,  g_attn);
    cudaGetSymbolAddress((void**)&xz,    g_xz);
    cudaGetSymbolAddress((void**)&y,     g_y);
    cudaGetSymbolAddress((void**)&x1,    g_x1);
    cudaGetSymbolAddress((void**)&h2,    g_h2);
    cudaGetSymbolAddress((void**)&hid,   g_hid);
    cudaGetSymbolAddress((void**)&xc,    g_xc);
    cudaGetSymbolAddress((void**)&dbl,   g_dbl);
    cudaGetSymbolAddress((void**)&dtT,   g_dtT);

    static cudaStream_t s_attn = nullptr;
    static cudaEvent_t ev_fork = nullptr, ev_join = nullptr;
    if (!s_attn){
        cudaStreamCreateWithFlags(&s_attn, cudaStreamNonBlocking);
        cudaEventCreateWithFlags(&ev_fork, cudaEventDisableTiming);
        cudaEventCreateWithFlags(&ev_join, cudaEventDisableTiming);
    }

    const int SM64  = 3*(2048 + 64*32)*4;            // 48 KB
    const int SM128 = 3*(2048 + 128*32)*4;           // 72 KB
    const int SMQI  = (8192 + 3*4096)*4;             // 80 KB
    const int SMFG  = (3*(2048+128*32) + 4*2048)*4;  // 104 KB
    cudaFuncSetAttribute(qkv_ln_gemm,          cudaFuncAttributeMaxDynamicSharedMemorySize, SMQI);
    cudaFuncSetAttribute(mma_gemm<128,1,0,0>,  cudaFuncAttributeMaxDynamicSharedMemorySize, SM128);
    cudaFuncSetAttribute(mma_gemm<64,0,0,0>,   cudaFuncAttributeMaxDynamicSharedMemorySize, SM64);
    cudaFuncSetAttribute(mma_gemm<64,0,1,1>,   cudaFuncAttributeMaxDynamicSharedMemorySize, SM64);
    cudaFuncSetAttribute(mma_gemm<64,3,0,0>,   cudaFuncAttributeMaxDynamicSharedMemorySize, SM64);
    cudaFuncSetAttribute(fused_out_gate,       cudaFuncAttributeMaxDynamicSharedMemorySize, SMFG);

    // fused LN1 + merged qkv/in_proj GEMM
    qkv_ln_gemm<<<dim3(7,196), 256, SMQI>>>(x, ln1_g, ln1_b, qkv_w, qkv_b, in_w, in_b, qkv, xz);

    // ---- fork: attention branch on s_attn ----
    cudaEventRecord(ev_fork, 0);
    cudaStreamWaitEvent(s_attn, ev_fork, 0);
    attn_kernel<<<NWIN*4, 128, 0, s_attn>>>(rpb);
    mma_gemm<64,0,0,0><<<dim3(2,196), 256, SM64, s_attn>>>(awb, proj_w, proj_b, attn, 128, 128, nullptr, nullptr, nullptr);
    cudaEventRecord(ev_join, s_attn);

    // ---- mamba branch on default stream ----
    conv_kernel<<<BATCH*98, 256>>>(conv_w, conv_b);
    // x_proj GEMM + fused dt_proj -> dbl, dtT
    mma_gemm<64,0,1,1><<<dim3(1,196), 256, SM64>>>(xc, xproj_w, nullptr, dbl, 40, 256, dtw, dtb, dtT);
    scan_phase1<<<(BATCH*NCH*128)/8, 256>>>(A_log);
    scan_phase2<<<128, 128>>>(A_log);
    scan_phase3<<<(BATCH*NCH*128)/8, 256>>>(A_log, Dp);

    // ---- join, then fused out_proj+gate+LN2, MLP ----
    cudaStreamWaitEvent(0, ev_join, 0);
    fused_out_gate<<<dim3(1,196), 256, SMFG>>>(y, out_w, out_b, gate_w, gate_b,
                                               x, attn, x1, ln2_g, ln2_b, h2);
    mma_gemm<128,1,0,0><<<dim3(4,196), 256, SM128>>>(h2, mlp_w1, mlp_b1, hid, 512, 128, nullptr, nullptr, nullptr);
    mma_gemm<64,3,0,0><<<dim3(2,196), 256, SM64>>>(hid, mlp_w2, mlp_b2, out, 128, 512, x1, nullptr, nullptr);

    (void)in_sizes; (void)n_in; (void)out_size;
}

// round 17
// speedup vs baseline: 1.0545x; 1.0545x over previous
#include <cuda_runtime.h>
#include <math.h>
#include <stdint.h>

#define TOK   12544
#define BATCH 4
#define LSEQ  3136
#define NWIN  256
#define NCH   49
#define CH    64

// ---------------- scratch ----------------
__device__ float g_xn[TOK*128];
__device__ float g_qkv[TOK*384];
__device__ float g_awb[TOK*128];
__device__ float g_attn[TOK*128];
__device__ float g_xz[TOK*512];
__device__ float g_xc[TOK*256];
__device__ float g_xcT[256*TOK];
__device__ float g_dtT[256*TOK];
__device__ float g_dbl[TOK*40];
__device__ float g_y[TOK*256];
__device__ float g_x1[TOK*128];
__device__ float g_h2[TOK*128];
__device__ float g_hid[TOK*512];
__device__ float g_hend[BATCH*NCH*256*16];
__device__ float g_hin[BATCH*NCH*256*16];
__device__ float g_sumdt[BATCH*NCH*256];

__device__ __forceinline__ float gelu_f(float x){ return 0.5f*x*(1.f+erff(x*0.70710678118f)); }
__device__ __forceinline__ uint32_t smem_u32(const void* p){
    uint32_t a; asm("{ .reg .u64 t; cvta.to.shared.u64 t, %1; cvt.u32.u64 %0, t; }" : "=r"(a) : "l"(p)); return a;
}
__device__ __forceinline__ void cpa16(uint32_t dst, const void* src){
    asm volatile("cp.async.cg.shared.global [%0], [%1], 16;" :: "r"(dst), "l"(src));
}
__device__ __forceinline__ void cpa16z(uint32_t dst, const void* src){
    asm volatile("cp.async.cg.shared.global [%0], [%1], 16, 0;" :: "r"(dst), "l"(src));
}
__device__ __forceinline__ void ldsm4(uint32_t* d, uint32_t addr){
    asm volatile("ldmatrix.sync.aligned.m8n8.x4.shared.b16 {%0,%1,%2,%3}, [%4];"
        : "=r"(d[0]),"=r"(d[1]),"=r"(d[2]),"=r"(d[3]) : "r"(addr));
}
__device__ __forceinline__ void mma8(float* c, const uint32_t* a, const uint32_t* b){
    asm volatile("mma.sync.aligned.m16n8k8.row.col.f32.tf32.tf32.f32 "
        "{%0,%1,%2,%3}, {%4,%5,%6,%7}, {%8,%9}, {%0,%1,%2,%3};"
        : "+f"(c[0]),"+f"(c[1]),"+f"(c[2]),"+f"(c[3])
        : "r"(a[0]),"r"(a[1]),"r"(a[2]),"r"(a[3]), "r"(b[0]),"r"(b[1]));
}

// ================= cp.async + ldmatrix tf32 mma GEMM =================
// EPI: 0 none, 1 gelu, 3 residual(e0). AG: A=[e1|e2] gather. NP pad. QI merged qkv+in_proj.
template<int NT, int EPI, int AG, int NP, int QI>
__global__ __launch_bounds__(256)
void mma_gemm(const float* __restrict__ A, const float* __restrict__ W,
              const float* __restrict__ bias, float* __restrict__ C,
              int Nout, int K,
              const float* __restrict__ e0, const float* __restrict__ e1,
              const float* __restrict__ e2)
{
    extern __shared__ float sm[];
    const int NW  = NT/32;
    const int MW  = 8/NW;
    const int MT  = 64/(16*MW);
    const int STG = 2048 + NT*32;
    const int BCH = (NT*8)/256;
    uint32_t sbase = smem_u32(sm);
    int tid = threadIdx.x, wid = tid>>5, lane = tid&31;
    int warp_n = wid % NW, warp_m = wid / NW;
    int bm = blockIdx.y*64, bn = blockIdx.x*NT;
    int m0 = warp_m * MT * 16;

    float acc[MT][4][4];
    #pragma unroll
    for (int i=0;i<MT;i++)
        #pragma unroll
        for (int j=0;j<4;j++)
            #pragma unroll
            for (int q=0;q<4;q++) acc[i][j][q]=0.f;

    auto issue = [&](int kt){
        int st = kt % 3;
        uint32_t abase = sbase + (uint32_t)st*STG*4;
        uint32_t bbase = abase + 2048*4;
        int kc = kt*32;
        #pragma unroll
        for (int i=0;i<2;i++){
            int ch = tid + i*256;
            int row = ch>>3, col = (ch&7)*4;
            uint32_t dst = abase + (uint32_t)(row*32 + (col ^ ((row&7)<<2)))*4;
            const float* src;
            if (AG){
                int kg = kc + col;
                src = (kg<128) ? e1 + (size_t)(bm+row)*128 + kg
                               : e2 + (size_t)(bm+row)*128 + (kg-128);
            } else {
                src = A + (size_t)(bm+row)*K + kc + col;
            }
            cpa16(dst, src);
        }
        #pragma unroll
        for (int i=0;i<BCH;i++){
            int ch = tid + i*256;
            int row = ch>>3, col = (ch&7)*4;
            uint32_t dst = bbase + (uint32_t)(row*32 + (col ^ ((row&7)<<2)))*4;
            if (QI){
                int rw = bn + row;
                const float* src = (rw < 384) ? W + (size_t)rw*K + kc + col
                                              : e1 + (size_t)(rw-384)*K + kc + col;
                cpa16(dst, src);
            } else if (NP && (bn+row) >= Nout) {
                cpa16z(dst, W);
            } else {
                cpa16(dst, W + (size_t)(bn+row)*K + kc + col);
            }
        }
        asm volatile("cp.async.commit_group;" ::: "memory");
    };

    int KT = K >> 5;
    issue(0);
    issue(1);

    int a_r  = m0 + (lane&7) + ((lane>>3)&1)*8;
    int a_cq = (lane>>4)*4;
    int b_nb = warp_n*32 + ((lane>>4))*8 + (lane&7);
    int b_kq = ((lane>>3)&1)*4;

    for (int kt=0; kt<KT; kt++){
        if (kt == KT-1) asm volatile("cp.async.wait_group 0;" ::: "memory");
        else            asm volatile("cp.async.wait_group 1;" ::: "memory");
        __syncthreads();
        if (kt+2 < KT) issue(kt+2);

        uint32_t abase = sbase + (uint32_t)((kt%3)*STG)*4;
        uint32_t bbase = abase + 2048*4;
        #pragma unroll
        for (int ks=0; ks<4; ks++){
            uint32_t af[MT][4];
            #pragma unroll
            for (int i=0;i<MT;i++){
                int r = a_r + i*16;
                int c = (ks*8 + a_cq) ^ ((r&7)<<2);
                ldsm4(af[i], abase + (uint32_t)(r*32 + c)*4);
            }
            uint32_t bf[2][4];
            #pragma unroll
            for (int j2=0;j2<2;j2++){
                int n = b_nb + j2*16;
                int c = (ks*8 + b_kq) ^ ((n&7)<<2);
                ldsm4(bf[j2], bbase + (uint32_t)(n*32 + c)*4);
            }
            #pragma unroll
            for (int i=0;i<MT;i++)
                #pragma unroll
                for (int j2=0;j2<2;j2++)
                    #pragma unroll
                    for (int jj=0;jj<2;jj++)
                        mma8(acc[i][2*j2+jj], af[i], &bf[j2][2*jj]);
        }
    }

    #pragma unroll
    for (int i=0;i<MT;i++){
        #pragma unroll
        for (int j=0;j<4;j++){
            int n = bn + warp_n*32 + j*8 + 2*(lane&3);
            if (NP && n >= Nout) continue;
            #pragma unroll
            for (int half=0; half<2; half++){
                int m = bm + m0 + i*16 + (lane>>2) + half*8;
                float vx = acc[i][j][half*2+0];
                float vy = acc[i][j][half*2+1];
                if (QI){
                    if (bn < 384){
                        float2 bv = *(const float2*)(bias + n);
                        vx += bv.x; vy += bv.y;
                        *(float2*)(C + (size_t)m*384 + n) = make_float2(vx, vy);
                    } else {
                        int n2 = n - 384;
                        float2 bv = *(const float2*)(e2 + n2);
                        vx += bv.x; vy += bv.y;
                        *(float2*)((float*)e0 + (size_t)m*512 + n2) = make_float2(vx, vy);
                    }
                    continue;
                }
                float2 bv = bias ? *(const float2*)(bias + n) : make_float2(0.f,0.f);
                vx += bv.x; vy += bv.y;
                size_t idx = (size_t)m*Nout + n;
                if (EPI == 1){
                    vx = gelu_f(vx); vy = gelu_f(vy);
                } else if (EPI == 3){
                    float2 r0 = *(const float2*)(e0 + idx);
                    vx += r0.x; vy += r0.y;
                }
                *(float2*)(C + idx) = make_float2(vx, vy);
            }
        }
    }
}

// ================= fused out_proj + gate + LN2 =================
__global__ __launch_bounds__(256)
void fused_out_gate(const float* __restrict__ y, const float* __restrict__ out_w,
                    const float* __restrict__ out_b,
                    const float* __restrict__ gate_w, const float* __restrict__ gate_b,
                    const float* __restrict__ x, const float* __restrict__ attn,
                    float* __restrict__ x1,
                    const float* __restrict__ ln_g, const float* __restrict__ ln_b,
                    float* __restrict__ h2)
{
    extern __shared__ float sm[];
    const int NT = 128, NW = 4, MT = 2;
    const int STG = 2048 + NT*32;
    float* msbuf = sm + 3*STG;
    uint32_t sbase = smem_u32(sm);
    uint32_t msbase = sbase + (uint32_t)(3*STG)*4;
    int tid = threadIdx.x, wid = tid>>5, lane = tid&31;
    int warp_n = wid % NW, warp_m = wid / NW;
    int bm = blockIdx.y*64;
    int m0 = warp_m * MT * 16;

    float acc[MT][4][4];
    #pragma unroll
    for (int i=0;i<MT;i++)
        #pragma unroll
        for (int j=0;j<4;j++)
            #pragma unroll
            for (int q=0;q<4;q++) acc[i][j][q]=0.f;

    int a_r  = m0 + (lane&7) + ((lane>>3)&1)*8;
    int a_cq = (lane>>4)*4;
    int b_nb = warp_n*32 + ((lane>>4))*8 + (lane&7);
    int b_kq = ((lane>>3)&1)*4;

    auto issueA = [&](int kt){
        int st = kt % 3;
        uint32_t abase = sbase + (uint32_t)st*STG*4;
        uint32_t bbase = abase + 2048*4;
        int kc = kt*32;
        #pragma unroll
        for (int i=0;i<2;i++){
            int ch = tid + i*256;
            int row = ch>>3, col = (ch&7)*4;
            uint32_t dst = abase + (uint32_t)(row*32 + (col ^ ((row&7)<<2)))*4;
            cpa16(dst, y + (size_t)(bm+row)*256 + kc + col);
        }
        #pragma unroll
        for (int i=0;i<4;i++){
            int ch = tid + i*256;
            int row = ch>>3, col = (ch&7)*4;
            uint32_t dst = bbase + (uint32_t)(row*32 + (col ^ ((row&7)<<2)))*4;
            cpa16(dst, out_w + (size_t)row*256 + kc + col);
        }
        asm volatile("cp.async.commit_group;" ::: "memory");
    };
    issueA(0); issueA(1);
    for (int kt=0; kt<8; kt++){
        if (kt == 7) asm volatile("cp.async.wait_group 0;" ::: "memory");
        else         asm volatile("cp.async.wait_group 1;" ::: "memory");
        __syncthreads();
        if (kt+2 < 8) issueA(kt+2);
        uint32_t abase = sbase + (uint32_t)((kt%3)*STG)*4;
        uint32_t bbase = abase + 2048*4;
        #pragma unroll
        for (int ks=0; ks<4; ks++){
            uint32_t af[MT][4];
            #pragma unroll
            for (int i=0;i<MT;i++){
                int r = a_r + i*16;
                int c = (ks*8 + a_cq) ^ ((r&7)<<2);
                ldsm4(af[i], abase + (uint32_t)(r*32 + c)*4);
            }
            uint32_t bf[2][4];
            #pragma unroll
            for (int j2=0;j2<2;j2++){
                int n = b_nb + j2*16;
                int c = (ks*8 + b_kq) ^ ((n&7)<<2);
                ldsm4(bf[j2], bbase + (uint32_t)(n*32 + c)*4);
            }
            #pragma unroll
            for (int i=0;i<MT;i++)
                #pragma unroll
                for (int j2=0;j2<2;j2++)
                    #pragma unroll
                    for (int jj=0;jj<2;jj++)
                        mma8(acc[i][2*j2+jj], af[i], &bf[j2][2*jj]);
        }
    }
    __syncthreads();
    #pragma unroll
    for (int i=0;i<MT;i++){
        #pragma unroll
        for (int j=0;j<4;j++){
            int n = warp_n*32 + j*8 + 2*(lane&3);
            float2 bv = *(const float2*)(out_b + n);
            #pragma unroll
            for (int half=0; half<2; half++){
                int r = m0 + i*16 + (lane>>2) + half*8;
                float vx = acc[i][j][half*2+0] + bv.x;
                float vy = acc[i][j][half*2+1] + bv.y;
                int ktm = n>>5, c = n&31, sw = (r&7)<<2;
                msbuf[ktm*2048 + r*32 + (c^sw)]     = vx;
                msbuf[ktm*2048 + r*32 + ((c^sw)+1)] = vy;
            }
        }
    }
    __syncthreads();

    #pragma unroll
    for (int i=0;i<MT;i++)
        #pragma unroll
        for (int j=0;j<4;j++)
            #pragma unroll
            for (int q=0;q<4;q++) acc[i][j][q]=0.f;

    auto issueB = [&](int kt){
        int st = kt % 3;
        uint32_t abase = sbase + (uint32_t)st*STG*4;
        uint32_t bbase = abase + 2048*4;
        int bcol = (kt < 4) ? 128 + kt*32 : (kt-4)*32;
        if (kt >= 4){
            int acol = (kt-4)*32;
            #pragma unroll
            for (int i=0;i<2;i++){
                int ch = tid + i*256;
                int row = ch>>3, col = (ch&7)*4;
                uint32_t dst = abase + (uint32_t)(row*32 + (col ^ ((row&7)<<2)))*4;
                cpa16(dst, attn + (size_t)(bm+row)*128 + acol + col);
            }
        }
        #pragma unroll
        for (int i=0;i<4;i++){
            int ch = tid + i*256;
            int row = ch>>3, col = (ch&7)*4;
            uint32_t dst = bbase + (uint32_t)(row*32 + (col ^ ((row&7)<<2)))*4;
            cpa16(dst, gate_w + (size_t)row*256 + bcol + col);
        }
        asm volatile("cp.async.commit_group;" ::: "memory");
    };
    issueB(0); issueB(1);
    for (int kt=0; kt<8; kt++){
        if (kt == 7) asm volatile("cp.async.wait_group 0;" ::: "memory");
        else         asm volatile("cp.async.wait_group 1;" ::: "memory");
        __syncthreads();
        if (kt+2 < 8) issueB(kt+2);
        uint32_t abase = (kt < 4) ? (msbase + (uint32_t)kt*2048*4)
                                  : (sbase + (uint32_t)((kt%3)*STG)*4);
        uint32_t bbase = sbase + (uint32_t)((kt%3)*STG)*4 + 2048*4;
        #pragma unroll
        for (int ks=0; ks<4; ks++){
            uint32_t af[MT][4];
            #pragma unroll
            for (int i=0;i<MT;i++){
                int r = a_r + i*16;
                int c = (ks*8 + a_cq) ^ ((r&7)<<2);
                ldsm4(af[i], abase + (uint32_t)(r*32 + c)*4);
            }
            uint32_t bf[2][4];
            #pragma unroll
            for (int j2=0;j2<2;j2++){
                int n = b_nb + j2*16;
                int c = (ks*8 + b_kq) ^ ((n&7)<<2);
                ldsm4(bf[j2], bbase + (uint32_t)(n*32 + c)*4);
            }
            #pragma unroll
            for (int i=0;i<MT;i++)
                #pragma unroll
                for (int j2=0;j2<2;j2++)
                    #pragma unroll
                    for (int jj=0;jj<2;jj++)
                        mma8(acc[i][2*j2+jj], af[i], &bf[j2][2*jj]);
        }
    }

    float* xs = sm;
    __syncthreads();
    #pragma unroll
    for (int i=0;i<MT;i++){
        #pragma unroll
        for (int j=0;j<4;j++){
            int n = warp_n*32 + j*8 + 2*(lane&3);
            float2 bv = *(const float2*)(gate_b + n);
            #pragma unroll
            for (int half=0; half<2; half++){
                int r = m0 + i*16 + (lane>>2) + half*8;
                int m = bm + r;
                float vx = acc[i][j][half*2+0] + bv.x;
                float vy = acc[i][j][half*2+1] + bv.y;
                size_t idx = (size_t)m*128 + n;
                float2 r0 = *(const float2*)(x + idx);
                float2 r1 = *(const float2*)(attn + idx);
                int ktm = n>>5, c = n&31, sw = (r&7)<<2;
                float m2x = msbuf[ktm*2048 + r*32 + (c^sw)];
                float m2y = msbuf[ktm*2048 + r*32 + ((c^sw)+1)];
                float gx = 1.f/(1.f+__expf(-vx));
                float gy = 1.f/(1.f+__expf(-vy));
                vx = r0.x + gx*r1.x + (1.f-gx)*m2x;
                vy = r0.y + gy*r1.y + (1.f-gy)*m2y;
                *(float2*)(x1 + idx) = make_float2(vx, vy);
                xs[r*129 + n]     = vx;
                xs[r*129 + n + 1] = vy;
            }
        }
    }
    __syncthreads();
    #pragma unroll 1
    for (int rr=0; rr<8; rr++){
        int r = wid*8 + rr;
        float v0 = xs[r*129 + lane];
        float v1 = xs[r*129 + lane + 32];
        float v2 = xs[r*129 + lane + 64];
        float v3 = xs[r*129 + lane + 96];
        float s = v0+v1+v2+v3;
        #pragma unroll
        for (int o=16;o;o>>=1) s += __shfl_xor_sync(~0u, s, o);
        float mean = s * (1.f/128.f);
        float d0=v0-mean, d1=v1-mean, d2=v2-mean, d3=v3-mean;
        float q = d0*d0+d1*d1+d2*d2+d3*d3;
        #pragma unroll
        for (int o=16;o;o>>=1) q += __shfl_xor_sync(~0u, q, o);
        float rstd = rsqrtf(q*(1.f/128.f) + 1e-5f);
        size_t mb = (size_t)(bm + r)*128;
        h2[mb + lane]      = d0*rstd*ln_g[lane]      + ln_b[lane];
        h2[mb + lane + 32] = d1*rstd*ln_g[lane + 32] + ln_b[lane + 32];
        h2[mb + lane + 64] = d2*rstd*ln_g[lane + 64] + ln_b[lane + 64];
        h2[mb + lane + 96] = d3*rstd*ln_g[lane + 96] + ln_b[lane + 96];
    }
}

// ---------------- LayerNorm ----------------
__global__ void ln_kernel(const float* __restrict__ in, const float* __restrict__ g,
                          const float* __restrict__ b, float* __restrict__ out) {
    int warp = (blockIdx.x * blockDim.x + threadIdx.x) >> 5;
    int lane = threadIdx.x & 31;
    if (warp >= TOK) return;
    float4 v = ((const float4*)(in + (size_t)warp*128))[lane];
    float s = v.x+v.y+v.z+v.w;
    #pragma unroll
    for (int o=16;o;o>>=1) s += __shfl_xor_sync(~0u, s, o);
    float mean = s * (1.f/128.f);
    float dx=v.x-mean, dy=v.y-mean, dz=v.z-mean, dw=v.w-mean;
    float q = dx*dx+dy*dy+dz*dz+dw*dw;
    #pragma unroll
    for (int o=16;o;o>>=1) q += __shfl_xor_sync(~0u, q, o);
    float rstd = rsqrtf(q*(1.f/128.f) + 1e-5f);
    float4 gv = ((const float4*)g)[lane];
    float4 bv = ((const float4*)b)[lane];
    float4 ov;
    ov.x = dx*rstd*gv.x + bv.x;
    ov.y = dy*rstd*gv.y + bv.y;
    ov.z = dz*rstd*gv.z + bv.z;
    ov.w = dw*rstd*gv.w + bv.w;
    ((float4*)(out + (size_t)warp*128))[lane] = ov;
}

// ---------------- window attention ----------------
__global__ void attn_kernel(const float* __restrict__ rpb) {
    int w = blockIdx.x >> 2;
    int head = blockIdx.x & 3;
    int b = w >> 6, wh = (w >> 3) & 7, ww = w & 7;
    __shared__ float qs[49][32], ks[49][32], vs[49][32];
    __shared__ float sc[49][49];
    int tid = threadIdx.x;
    const float scale = 0.17677669529663689f;
    for (int i = tid; i < 49*32; i += 128) {
        int n = i >> 5, d = i & 31;
        int t = ((b*56 + wh*7 + n/7)*56 + ww*7 + n%7);
        const float* base = g_qkv + (size_t)t*384 + head*32 + d;
        qs[n][d] = base[0] * scale;
        ks[n][d] = base[128];
        vs[n][d] = base[256];
    }
    __syncthreads();
    for (int idx = tid; idx < 49*49; idx += 128) {
        int i = idx/49, j = idx%49;
        float s = 0.f;
        const float4* qp = (const float4*)qs[i];
        const float4* kp = (const float4*)ks[j];
        #pragma unroll
        for (int k=0;k<8;k++){ float4 a=qp[k], c=kp[k]; s += a.x*c.x+a.y*c.y+a.z*c.z+a.w*c.w; }
        int dr = i/7 - j/7 + 6, dc = i%7 - j%7 + 6;
        sc[i][j] = s + rpb[(dr*13+dc)*4 + head];
    }
    __syncthreads();
    if (tid < 49) {
        int i = tid;
        float m = -1e30f;
        for (int j=0;j<49;j++) m = fmaxf(m, sc[i][j]);
        float sum = 0.f;
        for (int j=0;j<49;j++){ float e=__expf(sc[i][j]-m); sc[i][j]=e; sum+=e; }
        float inv = 1.f/sum;
        for (int j=0;j<49;j++) sc[i][j] *= inv;
    }
    __syncthreads();
    for (int idx = tid; idx < 49*32; idx += 128) {
        int i = idx >> 5, d = idx & 31;
        float o = 0.f;
        for (int j=0;j<49;j++) o += sc[i][j]*vs[j][d];
        int t = ((b*56 + wh*7 + i/7)*56 + ww*7 + i%7);
        g_awb[(size_t)t*128 + head*32 + d] = o;
    }
}

// ---------------- tiled causal conv (k=4) + SiLU, dual-layout, float4 fill ----------------
__global__ __launch_bounds__(256) void conv_kernel(const float* __restrict__ cw,
                                                   const float* __restrict__ cb) {
    __shared__ float tile[19][256];
    int blk = blockIdx.x;                 // BATCH*196
    int b = blk / 196;
    int t0 = (blk % 196) * 16;
    int tid = threadIdx.x;
    for (int idx = tid; idx < 19*64; idx += 256){
        int row = idx >> 6, c4 = (idx & 63) << 2;
        int tg = t0 + row - 3;
        float4 v = (tg >= 0) ? *(const float4*)&g_xz[((size_t)(b*LSEQ + tg))*512 + c4]
                             : make_float4(0.f,0.f,0.f,0.f);
        *(float4*)&tile[row][c4] = v;
    }
    __syncthreads();
    int d = tid;
    float w0 = cw[d*4+0], w1 = cw[d*4+1], w2 = cw[d*4+2], w3 = cw[d*4+3];
    float bb = cb[d];
    float vals[16];
    #pragma unroll 4
    for (int tt = 0; tt < 16; tt++){
        float acc = bb
            + w0*tile[tt+0][d] + w1*tile[tt+1][d]
            + w2*tile[tt+2][d] + w3*tile[tt+3][d];
        float sg = 1.f/(1.f+__expf(-acc));
        float v = acc * sg;
        vals[tt] = v;
        g_xc[((size_t)(b*LSEQ + t0 + tt))*256 + d] = v;
    }
    float* dstT = g_xcT + (size_t)d*TOK + b*LSEQ + t0;
    #pragma unroll
    for (int i=0;i<4;i++)
        ((float4*)dstT)[i] = make_float4(vals[4*i+0], vals[4*i+1], vals[4*i+2], vals[4*i+3]);
}

// ---------------- dt_proj + softplus -> transposed dtT[d][t] ----------------
__global__ __launch_bounds__(256) void dtproj_kernel(const float* __restrict__ wt,
                                                     const float* __restrict__ bias){
    int t0 = blockIdx.x * 32;
    int d = threadIdx.x;
    float wr[8];
    #pragma unroll
    for (int k=0;k<8;k++) wr[k] = wt[d*8+k];
    float bb = bias[d];
    float vals[32];
    #pragma unroll 4
    for (int tt=0; tt<32; tt++){
        const float4* r = (const float4*)(g_dbl + (size_t)(t0+tt)*40);
        float4 r0 = r[0], r1 = r[1];
        float acc = bb + r0.x*wr[0] + r0.y*wr[1] + r0.z*wr[2] + r0.w*wr[3]
                       + r1.x*wr[4] + r1.y*wr[5] + r1.z*wr[6] + r1.w*wr[7];
        vals[tt] = (acc > 20.f) ? acc : log1pf(__expf(acc));
    }
    float* dst = g_dtT + (size_t)d*TOK + t0;
    #pragma unroll
    for (int i=0;i<8;i++)
        ((float4*)dst)[i] = make_float4(vals[4*i+0], vals[4*i+1], vals[4*i+2], vals[4*i+3]);
}

// ============ chunk-parallel selective scan (staged loads, block-shared B/C) ============
__global__ __launch_bounds__(256) void scan_phase1(const float* __restrict__ A_log){
    __shared__ float sdt[8][2][64], sxc[8][2][64];
    __shared__ float sB[64][16];
    int warp = threadIdx.x >> 5, lane = threadIdx.x & 31;
    int gw = blockIdx.x * 8 + warp;
    int dpair = gw & 127;
    int d = dpair*2 + (lane >> 4);
    int s = lane & 15;
    float Aval = -__expf(A_log[d*16 + s]);
    int gw0 = blockIdx.x * 8;
    int chunk = (gw0 >> 7) % NCH;
    int b = gw0 / (128*NCH);
    int tb = b*LSEQ + chunk*CH;
    {
        int tt = threadIdx.x >> 2, q = (threadIdx.x & 3)*4;
        *(float4*)&sB[tt][q] = *(const float4*)&g_dbl[(size_t)(tb+tt)*40 + 8 + q];
    }
    {
        int rr = lane >> 4, c4 = (lane & 15)*4;
        int dbase = dpair*2;
        *(float4*)&sdt[warp][rr][c4] = *(const float4*)&g_dtT[(size_t)(dbase+rr)*TOK + tb + c4];
        *(float4*)&sxc[warp][rr][c4] = *(const float4*)&g_xcT[(size_t)(dbase+rr)*TOK + tb + c4];
    }
    __syncthreads();
    int rr = lane >> 4;
    float h = 0.f, sd = 0.f;
    #pragma unroll 1
    for (int g = 0; g < CH; g += 8) {
        #pragma unroll
        for (int u=0;u<8;u++){
            float dtv = sdt[warp][rr][g+u];
            float xcv = sxc[warp][rr][g+u];
            float Bv  = sB[g+u][s];
            sd += dtv;
            float a = __expf(dtv*Aval);
            h = a*h + dtv*Bv*xcv;
        }
    }
    size_t hidx = ((size_t)(b*NCH + chunk)*256 + d)*16 + s;
    g_hend[hidx] = h;
    if (s == 0) g_sumdt[(b*NCH + chunk)*256 + d] = sd;
}

__global__ __launch_bounds__(128) void scan_phase2(const float* __restrict__ A_log){
    int gw = (blockIdx.x*blockDim.x + threadIdx.x) >> 5;
    int lane = threadIdx.x & 31;
    int b = gw >> 7;
    int dpair = gw & 127;
    int d = dpair*2 + (lane >> 4);
    int s = lane & 15;
    float Aval = -__expf(A_log[d*16 + s]);
    float h = 0.f;
    size_t hb = ((size_t)(b*NCH)*256 + d)*16 + s;
    int    sb = (b*NCH)*256 + d;
    #pragma unroll 1
    for (int c0 = 0; c0 < 48; c0 += 8){
        float sd[8], he[8];
        #pragma unroll
        for (int u=0;u<8;u++){
            sd[u] = g_sumdt[sb + (c0+u)*256];
            he[u] = g_hend[hb + (size_t)(c0+u)*4096];
        }
        float dec[8];
        #pragma unroll
        for (int u=0;u<8;u++) dec[u] = __expf(Aval*sd[u]);
        #pragma unroll
        for (int u=0;u<8;u++){
            g_hin[hb + (size_t)(c0+u)*4096] = h;
            h = dec[u]*h + he[u];
        }
    }
    g_hin[hb + (size_t)48*4096] = h;
}

__global__ __launch_bounds__(256) void scan_phase3(const float* __restrict__ A_log,
                                                   const float* __restrict__ Dp){
    __shared__ float part[8*32*33];
    __shared__ float sdt[8][2][64], sxc[8][2][64];
    __shared__ float sB[64][16], sC[64][16];
    int warp = threadIdx.x >> 5, lane = threadIdx.x & 31;
    int gw = blockIdx.x * 8 + warp;
    int dpair = gw & 127;
    int dbase = dpair*2;
    int d = dbase + (lane >> 4);
    int s = lane & 15;
    float Aval = -__expf(A_log[d*16 + s]);
    float dp0 = Dp[dbase], dp1 = Dp[dbase+1];
    int gw0 = blockIdx.x * 8;
    int chunk = (gw0 >> 7) % NCH;
    int b = gw0 / (128*NCH);
    int tb = b*LSEQ + chunk*CH;
    size_t hidx = ((size_t)(b*NCH + chunk)*256 + d)*16 + s;
    float h = g_hin[hidx];
    float* pp = part + warp*32*33 + lane*33;
    float* wp = part + warp*32*33;
    {
        int tt = threadIdx.x >> 2, q = (threadIdx.x & 3)*4;
        *(float4*)&sB[tt][q] = *(const float4*)&g_dbl[(size_t)(tb+tt)*40 + 8 + q];
        *(float4*)&sC[tt][q] = *(const float4*)&g_dbl[(size_t)(tb+tt)*40 + 24 + q];
    }
    {
        int rr = lane >> 4, c4 = (lane & 15)*4;
        *(float4*)&sdt[warp][rr][c4] = *(const float4*)&g_dtT[(size_t)(dbase+rr)*TOK + tb + c4];
        *(float4*)&sxc[warp][rr][c4] = *(const float4*)&g_xcT[(size_t)(dbase+rr)*TOK + tb + c4];
    }
    __syncthreads();
    int rr = lane >> 4;
    #pragma unroll 1
    for (int half = 0; half < 2; half++) {
        int base = half*32;
        #pragma unroll 1
        for (int g = 0; g < 32; g += 8) {
            #pragma unroll
            for (int u=0;u<8;u++){
                float dtv = sdt[warp][rr][base+g+u];
                float xcv = sxc[warp][rr][base+g+u];
                float Bv  = sB[base+g+u][s];
                float Cv  = sC[base+g+u][s];
                float a = __expf(dtv*Aval);
                h = a*h + dtv*Bv*xcv;
                pp[g+u] = h * Cv;
            }
        }
        __syncwarp();
        {
            int lu = lane;
            int t = tb + base + lu;
            float y0 = 0.f, y1 = 0.f;
            #pragma unroll
            for (int ss=0; ss<16; ss++){
                y0 += wp[ss*33 + lu];
                y1 += wp[(16+ss)*33 + lu];
            }
            float xc0 = sxc[warp][0][base+lu];
            float xc1 = sxc[warp][1][base+lu];
            float2 zv = *(const float2*)&g_xz[(size_t)t*512 + 256 + dbase];
            float yv0 = y0 + xc0*dp0;
            float yv1 = y1 + xc1*dp1;
            float sg0 = 1.f/(1.f+__expf(-zv.x));
            float sg1 = 1.f/(1.f+__expf(-zv.y));
            *(float2*)&g_y[(size_t)t*256 + dbase] = make_float2(yv0*zv.x*sg0, yv1*zv.y*sg1);
        }
        __syncwarp();
    }
}

// ---------------- launch ----------------
extern "C" void kernel_launch(void* const* d_in, const int* in_sizes, int n_in,
                              void* d_out, int out_size) {
    const float* x        = (const float*)d_in[0];
    const float* ln1_g    = (const float*)d_in[1];
    const float* ln1_b    = (const float*)d_in[2];
    const float* qkv_w    = (const float*)d_in[3];
    const float* qkv_b    = (const float*)d_in[4];
    const float* rpb      = (const float*)d_in[5];
    const float* proj_w   = (const float*)d_in[6];
    const float* proj_b   = (const float*)d_in[7];
    const float* in_w     = (const float*)d_in[8];
    const float* in_b     = (const float*)d_in[9];
    const float* conv_w   = (const float*)d_in[10];
    const float* conv_b   = (const float*)d_in[11];
    const float* xproj_w  = (const float*)d_in[12];
    const float* dtw      = (const float*)d_in[13];
    const float* dtb      = (const float*)d_in[14];
    const float* A_log    = (const float*)d_in[15];
    const float* Dp       = (const float*)d_in[16];
    const float* out_w    = (const float*)d_in[17];
    const float* out_b    = (const float*)d_in[18];
    const float* gate_w   = (const float*)d_in[19];
    const float* gate_b   = (const float*)d_in[20];
    const float* ln2_g    = (const float*)d_in[21];
    const float* ln2_b    = (const float*)d_in[22];
    const float* mlp_w1   = (const float*)d_in[23];
    const float* mlp_b1   = (const float*)d_in[24];
    const float* mlp_w2   = (const float*)d_in[25];
    const float* mlp_b2   = (const float*)d_in[26];
    float* out = (float*)d_out;

    float *xn, *qkv, *awb, *attn, *xz, *y, *x1, *h2, *hid, *xc, *dbl;
    cudaGetSymbolAddress((void**)&xn,    g_xn);
    cudaGetSymbolAddress((void**)&qkv,   g_qkv);
    cudaGetSymbolAddress((void**)&awb,   g_awb);
    cudaGetSymbolAddress((void**)&attn,  g_attn);
    cudaGetSymbolAddress((void**)&xz,    g_xz);
    cudaGetSymbolAddress((void**)&y,     g_y);
    cudaGetSymbolAddress((void**)&x1,    g_x1);
    cudaGetSymbolAddress((void**)&h2,    g_h2);
    cudaGetSymbolAddress((void**)&hid,   g_hid);
    cudaGetSymbolAddress((void**)&xc,    g_xc);
    cudaGetSymbolAddress((void**)&dbl,   g_dbl);

    static cudaStream_t s_attn = nullptr;
    static cudaEvent_t ev_fork = nullptr, ev_join = nullptr;
    if (!s_attn){
        cudaStreamCreateWithFlags(&s_attn, cudaStreamNonBlocking);
        cudaEventCreateWithFlags(&ev_fork, cudaEventDisableTiming);
        cudaEventCreateWithFlags(&ev_join, cudaEventDisableTiming);
    }

    const int SM64  = 3*(2048 + 64*32)*4;            // 48 KB
    const int SM128 = 3*(2048 + 128*32)*4;           // 72 KB
    const int SMFG  = (3*(2048+128*32) + 4*2048)*4;  // 104 KB
    cudaFuncSetAttribute(mma_gemm<128,0,0,0,1>, cudaFuncAttributeMaxDynamicSharedMemorySize, SM128);
    cudaFuncSetAttribute(mma_gemm<128,1,0,0,0>, cudaFuncAttributeMaxDynamicSharedMemorySize, SM128);
    cudaFuncSetAttribute(mma_gemm<64,0,0,0,0>,  cudaFuncAttributeMaxDynamicSharedMemorySize, SM64);
    cudaFuncSetAttribute(mma_gemm<64,0,0,1,0>,  cudaFuncAttributeMaxDynamicSharedMemorySize, SM64);
    cudaFuncSetAttribute(mma_gemm<64,3,0,0,0>,  cudaFuncAttributeMaxDynamicSharedMemorySize, SM64);
    cudaFuncSetAttribute(fused_out_gate,        cudaFuncAttributeMaxDynamicSharedMemorySize, SMFG);

    // LN1
    ln_kernel<<<TOK/8, 256>>>(x, ln1_g, ln1_b, xn);
    // merged qkv + in_proj GEMM (N=896, K=128): n<384 -> qkv, else -> xz
    mma_gemm<128,0,0,0,1><<<dim3(7,196), 256, SM128>>>(xn, qkv_w, qkv_b, qkv, 384, 128, xz, in_w, in_b);

    // ---- fork: attention branch on s_attn ----
    cudaEventRecord(ev_fork, 0);
    cudaStreamWaitEvent(s_attn, ev_fork, 0);
    attn_kernel<<<NWIN*4, 128, 0, s_attn>>>(rpb);
    mma_gemm<64,0,0,0,0><<<dim3(2,196), 256, SM64, s_attn>>>(awb, proj_w, proj_b, attn, 128, 128, nullptr, nullptr, nullptr);
    cudaEventRecord(ev_join, s_attn);

    // ---- mamba branch on default stream ----
    conv_kernel<<<BATCH*196, 256>>>(conv_w, conv_b);
    mma_gemm<64,0,0,1,0><<<dim3(1,196), 256, SM64>>>(xc, xproj_w, nullptr, dbl, 40, 256, nullptr, nullptr, nullptr);
    dtproj_kernel<<<TOK/32, 256>>>(dtw, dtb);
    scan_phase1<<<(BATCH*NCH*128)/8, 256>>>(A_log);
    scan_phase2<<<128, 128>>>(A_log);
    scan_phase3<<<(BATCH*NCH*128)/8, 256>>>(A_log, Dp);

    // ---- join, then fused out_proj+gate+LN2, MLP ----
    cudaStreamWaitEvent(0, ev_join, 0);
    fused_out_gate<<<dim3(1,196), 256, SMFG>>>(y, out_w, out_b, gate_w, gate_b,
                                               x, attn, x1, ln2_g, ln2_b, h2);
    mma_gemm<128,1,0,0,0><<<dim3(4,196), 256, SM128>>>(h2, mlp_w1, mlp_b1, hid, 512, 128, nullptr, nullptr, nullptr);
    mma_gemm<64,3,0,0,0><<<dim3(2,196), 256, SM64>>>(hid, mlp_w2, mlp_b2, out, 128, 512, x1, nullptr, nullptr);

    (void)in_sizes; (void)n_in; (void)out_size;
}